// round 10
// baseline (speedup 1.0000x reference)
#include <cuda_runtime.h>

#define RFN 512
#define TN  32
#define KN  32
#define LN  2048
#define LH  1024             // L per half (l-split x2)
#define BK  32
#define NTILE (LH / BK)      // 32
#define STAGES 3
#define NPAIR 256
#define NCTA (NPAIR * 2)     // 512: pair = bid>>1, half = bid&1

__device__ unsigned long long g_part[NCTA][64][32];  // [cta][accidx][lane] 8.4 MB
__device__ int g_cnt[NPAIR];                         // per-pair tickets (reset after use)

// Packed double fp32 FMA / ADD (Blackwell f32x2) — PTX only.
__device__ __forceinline__ unsigned long long ffma2(unsigned long long a,
                                                    unsigned long long b,
                                                    unsigned long long c) {
    unsigned long long d;
    asm volatile("fma.rn.f32x2 %0, %1, %2, %3;" : "=l"(d) : "l"(a), "l"(b), "l"(c));
    return d;
}
__device__ __forceinline__ unsigned long long add2(unsigned long long a,
                                                   unsigned long long b) {
    unsigned long long d;
    asm volatile("add.rn.f32x2 %0, %1, %2;" : "=l"(d) : "l"(a), "l"(b), "l"(b));
    return d;
}
// (guard against typo above)
__device__ __forceinline__ unsigned long long add2f(unsigned long long a,
                                                    unsigned long long b) {
    unsigned long long d;
    asm volatile("add.rn.f32x2 %0, %1, %2;" : "=l"(d) : "l"(a), "l"(b));
    return d;
}

__device__ __forceinline__ void cp_async16(unsigned dst, const float* src) {
    asm volatile("cp.async.cg.shared.global [%0], [%1], 16;" :: "r"(dst), "l"(src) : "memory");
}

// 16B-chunk swizzle; branch b gets ^4 so its bank-quads complement branch a's.
#define SWZ(row, c4, b) ((((c4) ^ ((row) & 7) ^ ((b) << 2)) & 7))

// grid = 512: pair = bid>>1 (branches 2p,2p+1), h = bid&1 (l half)
// block = 32: lanes 0-15 -> branch 2p, lanes 16-31 -> branch 2p+1; 8t x 8k per lane.
__global__ __launch_bounds__(32)
void spyke_gemm(const float* __restrict__ rec,   // (T=32, C=1, RF=512, L=2048)
                const float* __restrict__ Wt,    // (RF=512, K=32, C=1, L=2048)
                float* __restrict__ out)         // (T, 1, K, RF)
{
    __shared__ __align__(16) float As[STAGES][2][TN][BK];   // 8 KB/stage
    __shared__ __align__(16) float Bs[STAGES][2][KN][BK];   // 8 KB/stage

    const int lane = threadIdx.x;
    const int bsel = lane >> 4;        // branch within pair
    const int l16  = lane & 15;
    const int rg   = l16 >> 2;         // 0..3 -> t rows {rg+4j, j=0..7}
    const int cg   = l16 & 3;          // 0..3 -> k cols {cg+4c, c=0..7}
    const int pair = blockIdx.x >> 1;
    const int lb   = (blockIdx.x & 1) * LH;

    const unsigned sA = (unsigned)__cvta_generic_to_shared(&As[0][0][0][0]);
    const unsigned sB = (unsigned)__cvta_generic_to_shared(&Bs[0][0][0][0]);

    unsigned long long acc[8][8];
#pragma unroll
    for (int j = 0; j < 8; j++)
#pragma unroll
        for (int c = 0; c < 8; c++) acc[j][c] = 0ull;

    // ---- tile filler: one address computation serves both A and B ----
    auto fill = [&](int s, int l0) {
#pragma unroll
        for (int i = 0; i < 16; i++) {
            int chunk = i * 32 + lane;           // 0..511: wb(1) x row(5) x c4(3)
            int wb  = chunk >> 8;
            int rem = chunk & 255;
            int row = rem >> 3, c4 = rem & 7;
            unsigned loff = (unsigned)(((s * 2 + wb) * TN + row) * BK * 4
                                       + SWZ(row, c4, wb) * 16);
            cp_async16(sA + loff, rec + ((size_t)row * RFN + pair * 2 + wb) * LN + l0 + c4 * 4);
            cp_async16(sB + loff, Wt + ((size_t)(pair * 2 + wb) * KN + row) * LN + l0 + c4 * 4);
        }
        asm volatile("cp.async.commit_group;" ::: "memory");
    };

    fill(0, lb);
    fill(1, lb + BK);

    int buf = 0, pf = STAGES - 1;
    for (int ti = 0; ti < NTILE; ti++) {
        asm volatile("cp.async.wait_group %0;" :: "n"(STAGES - 2) : "memory");
        __syncwarp();   // warp-private pipeline

        if (ti + STAGES - 1 < NTILE) {
            fill(pf, lb + (ti + STAGES - 1) * BK);
        } else {
            asm volatile("cp.async.commit_group;" ::: "memory");  // keep count in step
        }
        if (++pf == STAGES) pf = 0;

        // ---- compute tile ti: 8x8 per lane, j processed in two halves ----
#pragma unroll
        for (int lc4 = 0; lc4 < BK / 4; lc4++) {
            ulonglong2 bv[8];
#pragma unroll
            for (int c = 0; c < 8; c++) {
                const int row = cg + 4 * c;
                bv[c] = *(const ulonglong2*)&Bs[buf][bsel][row][SWZ(row, lc4, bsel) * 4];
            }
#pragma unroll
            for (int jh = 0; jh < 2; jh++) {
                ulonglong2 av[4];
#pragma unroll
                for (int j = 0; j < 4; j++) {
                    const int row = rg + 4 * (jh * 4 + j);
                    av[j] = *(const ulonglong2*)&As[buf][bsel][row][SWZ(row, lc4, bsel) * 4];
                }
#pragma unroll
                for (int j = 0; j < 4; j++)
#pragma unroll
                    for (int c = 0; c < 8; c++) {
                        acc[jh * 4 + j][c] = ffma2(av[j].x, bv[c].x, acc[jh * 4 + j][c]);
                        acc[jh * 4 + j][c] = ffma2(av[j].y, bv[c].y, acc[jh * 4 + j][c]);
                    }
            }
        }
        if (++buf == STAGES) buf = 0;
    }

    // ---- store packed partials (coalesced: 32 lanes x 8B per accidx) ----
    {
        unsigned long long* dst = &g_part[blockIdx.x][0][0];
#pragma unroll
        for (int j = 0; j < 8; j++)
#pragma unroll
            for (int c = 0; c < 8; c++)
                dst[(j * 8 + c) * 32 + lane] = acc[j][c];
    }

    __threadfence();
    int old = 0;
    if (lane == 0) old = atomicAdd(&g_cnt[pair], 1);
    old = __shfl_sync(0xffffffffu, old, 0);
    if (old != 1) return;
    __threadfence();   // acquire: both halves' partials visible

    // ---- finisher: combine halves, threshold, kWTA, output (lane = k) ----
    float* thr_sh = (float*)&As[0][0][0][0];     // dead tile smem: [t][33]

    for (int bs = 0; bs < 2; bs++) {
        const int r = pair * 2 + bs;
        float th[TN];
        int cnt = 0;
#pragma unroll
        for (int t = 0; t < TN; t++) {
            const int accidx = (t >> 2) * 8 + (lane >> 2);
            const int glane  = bs * 16 + (t & 3) * 4 + (lane & 3);
            unsigned long long p0 = g_part[pair * 2 + 0][accidx][glane];
            unsigned long long p1 = g_part[pair * 2 + 1][accidx][glane];
            unsigned long long s2 = add2f(p0, p1);
            float lo = __uint_as_float((unsigned)(s2 & 0xffffffffull));
            float hi = __uint_as_float((unsigned)(s2 >> 32));
            float pot = lo + hi;
            float tv = (pot > 20.0f) ? pot : 0.0f;
            th[t] = tv;
            cnt += (tv > 0.0f) ? 1 : 0;
            thr_sh[t * 33 + lane] = tv;          // for dynamic 'first' lookup
        }
        int first = 32 - cnt;
        if (first > 31) first = 31;              // cnt==0 -> 31 ; cnt>=1 -> 0..31
        float vals = thr_sh[first * 33 + lane];
        float vk = (cnt > 0) ? vals : 0.0f;
        float vmax = vk;
#pragma unroll
        for (int o = 16; o > 0; o >>= 1) {
            float ov = __shfl_xor_sync(0xffffffffu, vmax, o);
            vmax = (ov > vmax) ? ov : vmax;
        }
        const float v = vmax * 32.0f;
        const float total = (float)cnt * (vals + v);

        float cur = total;
        bool win = false;
#pragma unroll
        for (int it = 0; it < 4; it++) {
            float bvv = cur;
            int bi = lane;
#pragma unroll
            for (int o = 16; o > 0; o >>= 1) {
                float ov = __shfl_xor_sync(0xffffffffu, bvv, o);
                int   oi = __shfl_xor_sync(0xffffffffu, bi, o);
                if (ov > bvv || (ov == bvv && oi < bi)) { bvv = ov; bi = oi; }
            }
            if (lane == bi) {
                if (cur > 0.0f) win = true;      // valid = top_val != 0
                cur = -1.0f;                     // exclude from later rounds
            }
        }

#pragma unroll
        for (int t = 0; t < TN; t++) {
            out[(size_t)t * (KN * RFN) + (size_t)lane * RFN + r] =
                (win && th[t] > 0.0f) ? 1.0f : 0.0f;
        }
    }

    if (lane == 0) g_cnt[pair] = 0;              // reset for next graph replay
}

extern "C" void kernel_launch(void* const* d_in, const int* in_sizes, int n_in,
                              void* d_out, int out_size) {
    const float* rec = (const float*)d_in[0];   // rec_field (32,1,512,2048)
    const float* Wt  = (const float*)d_in[1];   // W (512,32,1,2048)
    // d_in[2] = reward — unused by the reference output
    float* out = (float*)d_out;                 // (32,1,32,512)
    spyke_gemm<<<NCTA, 32>>>(rec, Wt, out);
}